// round 16
// baseline (speedup 1.0000x reference)
#include <cuda_runtime.h>

// ov[b*256 + c] as float4s; g_ready is reset by a memset graph node each launch.
__device__ __align__(16) float d_ov[8 * 256];
__device__ int g_ready;

#define EPSF 1e-5f

// 512 blocks x 256 threads, all resident in wave 1 (occ>=4).
// Blocks 0..7: compute ov for batch b = blockIdx.x (float4 GEMVs, 4x64 k-slice),
//              publish via 8 same-address atomics (trivial), then do their img slice.
// Blocks 8..511: front-batch img loads (overlap with ov compute), spin, add, store.
__global__ void __launch_bounds__(256, 4)
fused_kernel(const float4* __restrict__ img,              // (8,1024,256) as float4
             const float*  __restrict__ param_tokens,     // (8,16)
             const float*  __restrict__ Wparam,           // (16,256)
             const float*  __restrict__ bparam,           // (256)
             const float*  __restrict__ ctx_g,            // (256)
             const float*  __restrict__ ctx_b,            // (256)
             const float4* __restrict__ Wkv4,             // (256,512): row k = f4 [k*128, +128)
             const float4* __restrict__ Wout4,            // (256,256): row k = f4 [k*64, +64)
             const float4* __restrict__ bout4,            // (256) as float4
             float4* __restrict__ out)                    // (8,1024,256) as float4
{
    const int bid = blockIdx.x;
    const int tid = threadIdx.x;
    const int t   = bid * 256 + tid;       // global float4 index base, 0..131071
    const int c4g = t & 63;                // float4 index within channel dim
    const int b0  = t >> 16;               // 0 or 1
    const float4* ovp = reinterpret_cast<const float4*>(d_ov);

    __shared__ float  s_ln[256];
    __shared__ float  s_v[256];
    __shared__ float4 s_part[4 * 65];      // padded stride 65
    __shared__ float  s_red[16];

    float4 a0, a1, a2, a3;

    if (bid >= 8) {
        // ---- consumers: front-batch img loads; they stream during ov compute ----
        a0 = img[t];
        a1 = img[t + 131072];
        a2 = img[t + 262144];
        a3 = img[t + 393216];
    } else {
        // ================= producer: ov for batch b = bid =================
        const int b  = bid;
        const int c4 = tid & 63;           // float4 column group
        const int sl = tid >> 6;           // k-slice 0..3
        const int kb = sl * 64;

        // ---- ctx[c] = param_tokens[b] @ Wparam + bparam (thread = channel) ----
        float ctx = bparam[tid];
        const float* pt = param_tokens + b * 16;
#pragma unroll
        for (int p = 0; p < 16; ++p)
            ctx = fmaf(__ldg(&pt[p]), Wparam[p * 256 + tid], ctx);

        // ---- LN stats: block reduce over 256 ----
        float ss = ctx, qq = ctx * ctx;
#pragma unroll
        for (int o = 16; o > 0; o >>= 1) {
            ss += __shfl_down_sync(0xffffffffu, ss, o);
            qq += __shfl_down_sync(0xffffffffu, qq, o);
        }
        const int warp = tid >> 5, lane = tid & 31;
        if (lane == 0) { s_red[warp] = ss; s_red[8 + warp] = qq; }
        __syncthreads();
        if (tid < 32) {
            float s2 = (tid < 8) ? s_red[tid]     : 0.0f;
            float q2 = (tid < 8) ? s_red[8 + tid] : 0.0f;
#pragma unroll
            for (int o = 4; o > 0; o >>= 1) {
                s2 += __shfl_down_sync(0xffffffffu, s2, o);
                q2 += __shfl_down_sync(0xffffffffu, q2, o);
            }
            if (tid == 0) { s_red[0] = s2; s_red[1] = q2; }
        }
        __syncthreads();
        const float mean = s_red[0] * (1.0f / 256.0f);
        const float var  = s_red[1] * (1.0f / 256.0f) - mean * mean;
        const float rinv = rsqrtf(var + EPSF);
        s_ln[tid] = fmaf((ctx - mean) * rinv, ctx_g[tid], ctx_b[tid]);
        __syncthreads();

        // ---- GEMV1 slice: acc = sum_{i<64} ln[kb+i] * WkvV[kb+i, c4] ----
        {
            const float4* wk = Wkv4 + 64 + c4;     // V half, column group c4
            float4 acc = make_float4(0.f, 0.f, 0.f, 0.f);
#pragma unroll 16
            for (int i = 0; i < 64; ++i) {
                const float  f = s_ln[kb + i];
                const float4 w = wk[(kb + i) * 128];
                acc.x = fmaf(f, w.x, acc.x);
                acc.y = fmaf(f, w.y, acc.y);
                acc.z = fmaf(f, w.z, acc.z);
                acc.w = fmaf(f, w.w, acc.w);
            }
            s_part[sl * 65 + c4] = acc;
        }
        __syncthreads();
        if (tid < 64) {
            const float4 p0 = s_part[tid],       p1 = s_part[65 + tid];
            const float4 p2 = s_part[130 + tid], p3 = s_part[195 + tid];
            float4 v;
            v.x = (p0.x + p1.x) + (p2.x + p3.x);
            v.y = (p0.y + p1.y) + (p2.y + p3.y);
            v.z = (p0.z + p1.z) + (p2.z + p3.z);
            v.w = (p0.w + p1.w) + (p2.w + p3.w);
            reinterpret_cast<float4*>(s_v)[tid] = v;
        }
        __syncthreads();

        // ---- GEMV2 slice: acc = sum_{i<64} v[kb+i] * Wout[kb+i, c4] ----
        {
            const float4* wo = Wout4 + c4;
            float4 acc = make_float4(0.f, 0.f, 0.f, 0.f);
#pragma unroll 16
            for (int i = 0; i < 64; ++i) {
                const float  f = s_v[kb + i];
                const float4 w = wo[(kb + i) * 64];
                acc.x = fmaf(f, w.x, acc.x);
                acc.y = fmaf(f, w.y, acc.y);
                acc.z = fmaf(f, w.z, acc.z);
                acc.w = fmaf(f, w.w, acc.w);
            }
            s_part[sl * 65 + c4] = acc;
        }
        __syncthreads();
        if (tid < 64) {
            const float4 p0 = s_part[tid],       p1 = s_part[65 + tid];
            const float4 p2 = s_part[130 + tid], p3 = s_part[195 + tid];
            const float4 bo = bout4[tid];
            float4 o;
            o.x = bo.x + (p0.x + p1.x) + (p2.x + p3.x);
            o.y = bo.y + (p0.y + p1.y) + (p2.y + p3.y);
            o.z = bo.z + (p0.z + p1.z) + (p2.z + p3.z);
            o.w = bo.w + (p0.w + p1.w) + (p2.w + p3.w);
            reinterpret_cast<float4*>(d_ov)[b * 64 + tid] = o;
        }
        __syncthreads();
        if (tid == 0) {
            __threadfence();                 // release d_ov
            atomicAdd(&g_ready, 1);          // 8 total: negligible
        }
    }

    // ---- wait until all 8 ov batches are published (one thread spins) ----
    if (tid == 0) {
        volatile int* r = &g_ready;
        while (*r < 8) __nanosleep(32);
        __threadfence();                     // acquire before d_ov reads
    }
    __syncthreads();

    if (bid < 8) {                           // producers load their img slice now
        a0 = img[t];
        a1 = img[t + 131072];
        a2 = img[t + 262144];
        a3 = img[t + 393216];
    }

    const float4 o0 = ovp[(b0 + 0) * 64 + c4g];
    const float4 o1 = ovp[(b0 + 2) * 64 + c4g];
    const float4 o2 = ovp[(b0 + 4) * 64 + c4g];
    const float4 o3 = ovp[(b0 + 6) * 64 + c4g];

    out[t]          = make_float4(a0.x + o0.x, a0.y + o0.y, a0.z + o0.z, a0.w + o0.w);
    out[t + 131072] = make_float4(a1.x + o1.x, a1.y + o1.y, a1.z + o1.z, a1.w + o1.w);
    out[t + 262144] = make_float4(a2.x + o2.x, a2.y + o2.y, a2.z + o2.z, a2.w + o2.w);
    out[t + 393216] = make_float4(a3.x + o3.x, a3.y + o3.y, a3.z + o3.z, a3.w + o3.w);
    // NO reset here, NO g_done counter — reset is a memset node before the kernel.
}

extern "C" void kernel_launch(void* const* d_in, const int* in_sizes, int n_in,
                              void* d_out, int out_size)
{
    // metadata order:
    // 0 img_tokens (8,1024,256)  1 param_tokens (8,16)
    // 2 img_norm_g 3 img_norm_b  4 Wq            <- all dead (softmax collapse)
    // 5 Wparam (16,256)  6 bparam (256)
    // 7 ctx_norm_g (256) 8 ctx_norm_b (256)
    // 9 Wkv (256,512)   10 Wout (256,256)  11 bout (256)
    const float* img          = (const float*)d_in[0];
    const float* param_tokens = (const float*)d_in[1];
    const float* Wparam       = (const float*)d_in[5];
    const float* bparam       = (const float*)d_in[6];
    const float* ctx_g        = (const float*)d_in[7];
    const float* ctx_b        = (const float*)d_in[8];
    const float* Wkv          = (const float*)d_in[9];
    const float* Wout         = (const float*)d_in[10];
    const float* bout         = (const float*)d_in[11];
    float* out = (float*)d_out;

    // Reset the ready flag as a graph node (no device-side reset counters).
    void* g_ready_addr = nullptr;
    cudaGetSymbolAddress(&g_ready_addr, g_ready);
    cudaMemsetAsync(g_ready_addr, 0, sizeof(int), 0);

    fused_kernel<<<512, 256>>>((const float4*)img, param_tokens, Wparam, bparam,
                               ctx_g, ctx_b,
                               (const float4*)Wkv, (const float4*)Wout,
                               (const float4*)bout, (float4*)out);
}